// round 9
// baseline (speedup 1.0000x reference)
#include <cuda_runtime.h>
#include <cuda_fp16.h>
#include <cstdint>

// IntraAgg: segment-mean neighbor aggregation.
// Phase 1: convert features f32 -> fp16 table (halves the L2-capped gather bytes).
// Phase 2: warp-per-segment barrier-free per-thread cp.async ring gather.
//   d_in[0] features    float32 [100000*256]
//   d_in[1] neigh_idx   int32   [524288]
//   d_in[2] segment_ids int32   [524288] (sorted ascending)
//   d_in[3] self_feats  float32 [16384*256]
// output: float32 [16384*512] = concat(self - agg, agg)

#define D_FEAT   256
#define N_BATCH  16384
#define N_NODES  100000
#define STAGES   8                // ring: 8 rows = 4 groups of 2
#define TPB      64               // 2 warps, each owns one segment
#define WPB      2
#define ROW_B    (D_FEAT * 2)     // 512 bytes per fp16 row

__device__ int g_seg_start[N_BATCH + 1];
__device__ __align__(16) __half g_feat_h[(size_t)N_NODES * D_FEAT];  // 51.2 MB scratch

__global__ void seg_bounds_kernel(const int* __restrict__ seg_ids, int n_edges)
{
    const int e = blockIdx.x * blockDim.x + threadIdx.x;
    if (e >= n_edges) return;
    const int s_cur  = __ldg(seg_ids + e);
    const int s_prev = (e == 0) ? -1 : __ldg(seg_ids + e - 1);
    for (int b = s_prev + 1; b <= s_cur; ++b)
        g_seg_start[b] = e;
    if (e == n_edges - 1)
        for (int b = s_cur + 1; b <= N_BATCH; ++b)
            g_seg_start[b] = n_edges;
}

// 8 floats per thread: 2x float4 (evict-first) -> 8 halves (one 16B store)
__global__ void convert_kernel(const float* __restrict__ f, int n8)
{
    const int i = blockIdx.x * blockDim.x + threadIdx.x;
    if (i >= n8) return;
    const float4* s = reinterpret_cast<const float4*>(f) + 2 * (size_t)i;
    const float4 a = __ldcs(s);
    const float4 c = __ldcs(s + 1);
    __half2 h[4];
    h[0] = __floats2half2_rn(a.x, a.y);
    h[1] = __floats2half2_rn(a.z, a.w);
    h[2] = __floats2half2_rn(c.x, c.y);
    h[3] = __floats2half2_rn(c.z, c.w);
    *reinterpret_cast<uint4*>(g_feat_h + 8 * (size_t)i) = *reinterpret_cast<const uint4*>(h);
}

__device__ __forceinline__ uint32_t smem_u32(const void* p)
{
    return (uint32_t)__cvta_generic_to_shared(p);
}

__device__ __forceinline__ void cp16(uint32_t dst, const void* src)
{
    asm volatile("cp.async.cg.shared.global [%0], [%1], 16;"
                 :: "r"(dst), "l"(src) : "memory");
}

__device__ __forceinline__ void cp_commit()
{
    asm volatile("cp.async.commit_group;" ::: "memory");
}

__global__ __launch_bounds__(TPB) void intra_agg_kernel(
    const int* __restrict__ neigh_idx,
    const float* __restrict__ self_feats,
    float* __restrict__ out)
{
    // lane owns 16B (8 halves) of each row; no cross-thread smem sharing,
    // no barriers. Each warp handles one independent segment.
    __shared__ __align__(16) float4 buf[WPB][STAGES][32];

    const int w    = threadIdx.x >> 5;
    const int lane = threadIdx.x & 31;
    const int b    = blockIdx.x * WPB + w;

    const int start = g_seg_start[b];
    const int cnt   = g_seg_start[b + 1] - start;
    const int ngroups = (cnt + 1) >> 1;

    const char* fbase = reinterpret_cast<const char*>(g_feat_h);
    const size_t col = (size_t)lane * 16;

    // ---- prologue: up to 4 groups of 2 rows, one commit per group
    #pragma unroll
    for (int gj = 0; gj < 4; ++gj) {
        if (gj < ngroups) {
            const int r0 = 2 * gj;
            const int n0 = __ldg(neigh_idx + start + r0);
            cp16(smem_u32(&buf[w][r0][lane]), fbase + (size_t)n0 * ROW_B + col);
            if (r0 + 1 < cnt) {
                const int n1 = __ldg(neigh_idx + start + r0 + 1);
                cp16(smem_u32(&buf[w][r0 + 1][lane]), fbase + (size_t)n1 * ROW_B + col);
            }
            cp_commit();
        }
    }

    float2 acc0 = make_float2(0.f, 0.f);
    float2 acc1 = make_float2(0.f, 0.f);
    float2 acc2 = make_float2(0.f, 0.f);
    float2 acc3 = make_float2(0.f, 0.f);

    auto accum = [&](float4 raw) {
        const __half2* hp = reinterpret_cast<const __half2*>(&raw);
        float2 p;
        p = __half22float2(hp[0]); acc0.x += p.x; acc0.y += p.y;
        p = __half22float2(hp[1]); acc1.x += p.x; acc1.y += p.y;
        p = __half22float2(hp[2]); acc2.x += p.x; acc2.y += p.y;
        p = __half22float2(hp[3]); acc3.x += p.x; acc3.y += p.y;
    };

    // ---- steady state: wait_group 3 -> group g ready; consume 2 rows,
    // refill with group g+4, indices prefetched one iteration ahead.
    int g = 0;
    int nx0 = 0, nx1 = 0;
    if (4 < ngroups) {
        nx0 = __ldg(neigh_idx + start + 8);
        nx1 = (9 < cnt) ? __ldg(neigh_idx + start + 9) : nx0;
    }
    #pragma unroll 1
    for (; g + 4 < ngroups; ++g) {
        asm volatile("cp.async.wait_group 3;" ::: "memory");
        const int s0 = (2 * g) & (STAGES - 1);
        const float4 f0 = buf[w][s0][lane];
        const float4 f1 = buf[w][s0 + 1][lane];

        const int rr = 2 * (g + 4);
        cp16(smem_u32(&buf[w][s0][lane]), fbase + (size_t)nx0 * ROW_B + col);
        if (rr + 1 < cnt)
            cp16(smem_u32(&buf[w][s0 + 1][lane]), fbase + (size_t)nx1 * ROW_B + col);
        cp_commit();

        if (g + 5 < ngroups) {
            const int rn = 2 * (g + 5);
            nx0 = __ldg(neigh_idx + start + rn);
            nx1 = (rn + 1 < cnt) ? __ldg(neigh_idx + start + rn + 1) : nx0;
        }

        accum(f0);
        accum(f1);
    }

    // ---- tail
    asm volatile("cp.async.wait_group 0;" ::: "memory");
    #pragma unroll 1
    for (int r = 2 * g; r < cnt; ++r)
        accum(buf[w][r & (STAGES - 1)][lane]);

    const float inv = 1.0f / fmaxf((float)cnt, 1.0f);
    const float4 agg0 = make_float4(acc0.x * inv, acc0.y * inv, acc1.x * inv, acc1.y * inv);
    const float4 agg1 = make_float4(acc2.x * inv, acc2.y * inv, acc3.x * inv, acc3.y * inv);

    // lane owns feature elements [8*lane, 8*lane+8)
    const float4* sp = reinterpret_cast<const float4*>(self_feats + (size_t)b * D_FEAT) + 2 * lane;
    const float4 s0 = __ldcs(sp);
    const float4 s1 = __ldcs(sp + 1);
    const float4 d0 = make_float4(s0.x - agg0.x, s0.y - agg0.y, s0.z - agg0.z, s0.w - agg0.w);
    const float4 d1 = make_float4(s1.x - agg1.x, s1.y - agg1.y, s1.z - agg1.z, s1.w - agg1.w);

    float* orow = out + (size_t)b * (2 * D_FEAT);
    __stcs(reinterpret_cast<float4*>(orow) + 2 * lane, d0);
    __stcs(reinterpret_cast<float4*>(orow) + 2 * lane + 1, d1);
    __stcs(reinterpret_cast<float4*>(orow + D_FEAT) + 2 * lane, agg0);
    __stcs(reinterpret_cast<float4*>(orow + D_FEAT) + 2 * lane + 1, agg1);
}

extern "C" void kernel_launch(void* const* d_in, const int* in_sizes, int n_in,
                              void* d_out, int out_size)
{
    const float* features   = (const float*)d_in[0];
    const int*   neigh_idx  = (const int*)d_in[1];
    const int*   seg_ids    = (const int*)d_in[2];
    const float* self_feats = (const float*)d_in[3];
    float*       out        = (float*)d_out;

    const int n_edges = in_sizes[1];
    const int n_batch = in_sizes[3] / D_FEAT;   // 16384
    const int n8 = in_sizes[0] / 8;             // 8 floats per convert thread

    convert_kernel<<<(n8 + 255) / 256, 256>>>(features, n8);
    seg_bounds_kernel<<<(n_edges + 255) / 256, 256>>>(seg_ids, n_edges);
    intra_agg_kernel<<<n_batch / WPB, TPB>>>(neigh_idx, self_feats, out);
}